// round 6
// baseline (speedup 1.0000x reference)
#include <cuda_runtime.h>
#include <cuda_bf16.h>

#define NV 8192
#define EPSV 1e-5f
#define MAXSPAN 256        /* degree span bound; bins are bytes */
#define ECAP (1 << 22)
#define GRID 592           /* 4 blocks x 148 SMs — guaranteed co-resident */
#define TPB 256
#define NPART 256          /* base-term partition blocks */
#define PSIZE 32           /* NV / NPART */
#define NTRI (PSIZE * (PSIZE + 1) / 2)
#define EBLK (GRID - NPART)

// ------------- device state (static zero-init; reset by phase 4) -----------
__device__ int           g_deg[NV];
__device__ unsigned char g_bin[NV];
__device__ unsigned      g_edges[ECAP];
__device__ int           g_ecount;
__device__ int           g_dmin = 0x7fffffff;
__device__ int           g_dmax = 0;
__device__ double        g_sum;
__device__ float         g_Tbase[MAXSPAN * MAXSPAN];
__device__ float         g_Tdiff[MAXSPAN * MAXSPAN];
__device__ unsigned      g_barcnt[4];
__device__ unsigned      g_bargen[4];

// ------------- software grid barrier (self-resetting, replay-safe) ---------
__device__ __forceinline__ void gridbar(int i) {
    __syncthreads();
    if (threadIdx.x == 0) {
        __threadfence();
        unsigned gen = atomicAdd(&g_bargen[i], 0u);      // read gen BEFORE arrive
        unsigned t = atomicAdd(&g_barcnt[i], 1u);
        if (t == GRID - 1) {
            g_barcnt[i] = 0;                             // self-reset for next replay
            __threadfence();
            atomicAdd(&g_bargen[i], 1u);                 // release
        } else {
            while (atomicAdd(&g_bargen[i], 0u) == gen) {}
        }
        __threadfence();
    }
    __syncthreads();
}

__global__ void __launch_bounds__(TPB, 4)
k_all(const float* __restrict__ g, const float* __restrict__ params,
      float* __restrict__ out) {
    __shared__ int wsum[8], wbase[8], sbase;
    __shared__ int H[MAXSPAN];
    __shared__ int sbin[PSIZE];
    __shared__ double red[8];

    const int tid = threadIdx.x;
    const int lane = tid & 31, wid = tid >> 5;

    // ============ Phase 1: paired-row upper-triangle stream (~128MB) =======
    for (int pair = blockIdx.x; pair < NV / 2; pair += GRID) {
        int rA = pair, rB = NV - 1 - pair;
        const float4* rpA = (const float4*)(g + (size_t)rA * NV);
        const float4* rpB = (const float4*)(g + (size_t)rB * NV);
        int t0A = rA >> 2, t0B = rB >> 2;
        unsigned umA = 0, umB = 0;
#pragma unroll
        for (int k = 0; k < 8; k++) {
            int ia = t0A + tid + (k << 8);
            if (ia < NV / 4) {
                float4 v = __ldg(&rpA[ia]);
                int j0 = ia << 2;
                unsigned m = 0;
                if (v.x != 0.f && j0 + 0 >= rA) m |= 1u;
                if (v.y != 0.f && j0 + 1 >= rA) m |= 2u;
                if (v.z != 0.f && j0 + 2 >= rA) m |= 4u;
                if (v.w != 0.f && j0 + 3 >= rA) m |= 8u;
                umA |= m << (4 * k);
            }
            int ib = t0B + tid + (k << 8);
            if (ib < NV / 4) {
                float4 v = __ldg(&rpB[ib]);
                int j0 = ib << 2;
                unsigned m = 0;
                if (v.x != 0.f && j0 + 0 >= rB) m |= 1u;
                if (v.y != 0.f && j0 + 1 >= rB) m |= 2u;
                if (v.z != 0.f && j0 + 2 >= rB) m |= 4u;
                if (v.w != 0.f && j0 + 3 >= rB) m |= 8u;
                umB |= m << (4 * k);
            }
        }
        int cA = __popc(umA), cB = __popc(umB);
        int cnt = cA + cB;

        int dA = cA, dB = cB;
#pragma unroll
        for (int o = 16; o; o >>= 1) {
            dA += __shfl_down_sync(0xffffffffu, dA, o);
            dB += __shfl_down_sync(0xffffffffu, dB, o);
        }
        if (lane == 0) {
            if (dA) atomicAdd(&g_deg[rA], dA);
            if (dB) atomicAdd(&g_deg[rB], dB);
        }

        int inc = cnt;
#pragma unroll
        for (int o = 1; o < 32; o <<= 1) {
            int nn = __shfl_up_sync(0xffffffffu, inc, o);
            if (lane >= o) inc += nn;
        }
        if (lane == 31) wsum[wid] = inc;
        __syncthreads();
        if (tid == 0) {
            int run = 0;
            for (int w = 0; w < 8; w++) { wbase[w] = run; run += wsum[w]; }
            sbase = run ? atomicAdd(&g_ecount, run) : 0;
        }
        __syncthreads();

        int off = sbase + wbase[wid] + inc - cnt;
        unsigned m2 = umA;
        while (m2) {
            int b = __ffs(m2) - 1; m2 &= m2 - 1;
            int j = ((t0A + tid + ((b >> 2) << 8)) << 2) + (b & 3);
            if (off < ECAP) g_edges[off] = ((unsigned)rA << 13) | (unsigned)j;
            if (j > rA) atomicAdd(&g_deg[j], 1);
            off++;
        }
        m2 = umB;
        while (m2) {
            int b = __ffs(m2) - 1; m2 &= m2 - 1;
            int j = ((t0B + tid + ((b >> 2) << 8)) << 2) + (b & 3);
            if (off < ECAP) g_edges[off] = ((unsigned)rB << 13) | (unsigned)j;
            if (j > rB) atomicAdd(&g_deg[j], 1);
            off++;
        }
        __syncthreads();
    }
    gridbar(0);   // degrees + edge list complete

    // ============ Phase 2a: degree min/max =================================
    {
        int i = blockIdx.x * TPB + tid;
        int mn = 0x7fffffff, mx = 0;
        if (i < NV) { int v = g_deg[i]; mn = v; mx = v; }
#pragma unroll
        for (int o = 16; o; o >>= 1) {
            mn = min(mn, __shfl_down_sync(0xffffffffu, mn, o));
            mx = max(mx, __shfl_down_sync(0xffffffffu, mx, o));
        }
        if (lane == 0 && mx >= 0 && i < NV + 32) {
            atomicMin(&g_dmin, mn);
            atomicMax(&g_dmax, mx);
        }
    }
    gridbar(1);   // dmin/dmax final

    // ============ Phase 2b: bins + pow2-stride table =======================
    int dmin = g_dmin;
    int span = min(g_dmax - dmin + 1, MAXSPAN);
    int sh = 0;
    while ((1 << sh) < span) sh++;
    int stride = 1 << sh;
    {
        for (int i = blockIdx.x * TPB + tid; i < NV; i += GRID * TPB)
            g_bin[i] = (unsigned char)min(max(g_deg[i] - dmin, 0), span - 1);

        float alpha = params[0], beta = params[1], sigma = params[2];
        int total = span << sh;
        for (int idx = blockIdx.x * TPB + tid; idx < total; idx += GRID * TPB) {
            int b = idx >> sh;                 // j-side bin (beta)
            int a = idx & (stride - 1);        // i-side bin (alpha)
            float l0 = 0.f, ld = 0.f;
            if (a < span) {
                float s = alpha * (float)(dmin + a) + beta * (float)(dmin + b) + sigma;
                float p = 1.f / (1.f + expf(s));
                l0 = logf(1.f - p + EPSV);
                ld = logf(p + EPSV) - l0;
            }
            g_Tbase[idx] = l0;
            g_Tdiff[idx] = ld;
        }
    }
    gridbar(2);   // bins + tables ready

    // ============ Phase 3: base term + edge correction =====================
    double acc = 0.0;
    if (blockIdx.x < NPART) {
        int p = blockIdx.x;
        for (int b = tid; b < stride; b += TPB) H[b] = 0;
        __syncthreads();
        for (int i = tid; i < p * PSIZE; i += TPB)
            atomicAdd(&H[g_bin[i]], 1);
        if (tid < PSIZE) sbin[tid] = g_bin[p * PSIZE + tid];
        __syncthreads();

        int ncross = PSIZE << sh;
        for (int idx = tid; idx < ncross; idx += TPB) {
            int jj = idx >> sh;
            int b  = idx & (stride - 1);
            acc += (double)((float)H[b] * g_Tbase[(sbin[jj] << sh) + b]);
        }
        for (int idx = tid; idx < NTRI; idx += TPB) {
            int jj = (int)((sqrtf(8.f * (float)idx + 1.f) - 1.f) * 0.5f);
            while ((jj + 1) * (jj + 2) / 2 <= idx) jj++;
            while (jj * (jj + 1) / 2 > idx) jj--;
            int ii = idx - jj * (jj + 1) / 2;
            acc += (double)g_Tbase[(sbin[jj] << sh) + sbin[ii]];
        }
    } else {
        int ec = min(g_ecount, ECAP);
        for (int e = (blockIdx.x - NPART) * TPB + tid; e < ec; e += EBLK * TPB) {
            unsigned pk = g_edges[e];
            int bi = g_bin[pk >> 13];
            int bj = g_bin[pk & 8191u];
            acc += (double)g_Tdiff[(bj << sh) + bi];
        }
    }
#pragma unroll
    for (int o = 16; o; o >>= 1) acc += __shfl_down_sync(0xffffffffu, acc, o);
    if (lane == 0) red[wid] = acc;
    __syncthreads();
    if (tid == 0) {
        double t = 0.0;
        for (int w = 0; w < 8; w++) t += red[w];
        if (t != 0.0) atomicAdd(&g_sum, t);
    }
    gridbar(3);   // g_sum complete

    // ============ Phase 4: output + reset state for next replay ============
    if (blockIdx.x == 0) {
        if (tid == 0) out[0] = -(float)g_sum;
        for (int i = tid; i < NV; i += TPB) g_deg[i] = 0;
        if (tid == 0) {
            g_ecount = 0;
            g_sum = 0.0;
            g_dmin = 0x7fffffff;
            g_dmax = 0;
        }
    }
}

// ---------------- launch: ONE kernel node ----------------
extern "C" void kernel_launch(void* const* d_in, const int* in_sizes, int n_in,
                              void* d_out, int out_size) {
    const float* params = (const float*)d_in[0];  // [3]
    const float* graph  = (const float*)d_in[1];  // [8192*8192]
    k_all<<<GRID, TPB>>>(graph, params, (float*)d_out);
}

// round 9
// speedup vs baseline: 1.4314x; 1.4314x over previous
#include <cuda_runtime.h>
#include <cuda_bf16.h>

#define NV 8192
#define EPSV 1e-5f
#define SPAN 256            /* fixed bin range: deg in [0,255], no minmax pass */
#define SH 8                /* table row stride = 256, compile-time */
#define ECAP (1 << 22)
#define TPB 256
#define NPAIRS (NV / 2)     /* 4096 streaming blocks */
#define TFILL 64            /* table-fill blocks appended to k_main */
#define NPART 256           /* base-term partition blocks */
#define PSIZE 32            /* NV / NPART */
#define NTRI (PSIZE * (PSIZE + 1) / 2)
#define EBLK 448
#define GRID_BE (NPART + EBLK)

// ---------- device state (static zero-init; reset by k_baseedge finalizer) --
__device__ int      g_deg[NV];
__device__ unsigned g_edges[ECAP];
__device__ int      g_ecount;
__device__ int      g_done;
__device__ double   g_sum;
__device__ float    g_Tbase[SPAN * SPAN];   // log(1-p+eps),   [bj<<8 | bi]
__device__ float    g_Tdiff[SPAN * SPAN];   // log(p+eps)-log(1-p+eps)

// ---------------- K1: table fill (blocks 0..63) + paired-row stream --------
// Table depends only on params, so it rides for free alongside the 128MB
// memory-bound streaming phase instead of needing its own launch.
__global__ void __launch_bounds__(TPB) k_main(const float* __restrict__ g,
                                              const float* __restrict__ params) {
    const int tid = threadIdx.x;

    if (blockIdx.x < TFILL) {               // ---- table fill: 4 entries/thread
        float alpha = params[0], beta = params[1], sigma = params[2];
        for (int idx = blockIdx.x * TPB + tid; idx < SPAN * SPAN;
             idx += TFILL * TPB) {
            int b = idx >> SH;              // j-side bin (beta)
            int a = idx & (SPAN - 1);       // i-side bin (alpha)
            float s = alpha * (float)a + beta * (float)b + sigma;
            float p = 1.f / (1.f + expf(s));
            float l0 = logf(1.f - p + EPSV);
            g_Tbase[idx] = l0;
            g_Tdiff[idx] = logf(p + EPSV) - l0;
        }
        return;
    }

    // ---- paired-row upper-triangle stream (validated R4/R5 body) ----------
    int pair = blockIdx.x - TFILL;
    int rA = pair, rB = NV - 1 - pair;
    const float4* rpA = (const float4*)(g + (size_t)rA * NV);
    const float4* rpB = (const float4*)(g + (size_t)rB * NV);
    int t0A = rA >> 2, t0B = rB >> 2;
    unsigned umA = 0, umB = 0;
#pragma unroll
    for (int k = 0; k < 8; k++) {
        int ia = t0A + tid + (k << 8);
        if (ia < NV / 4) {
            float4 v = __ldcs(&rpA[ia]);    // streaming: don't pollute L2
            int j0 = ia << 2;
            unsigned m = 0;
            if (v.x != 0.f && j0 + 0 >= rA) m |= 1u;
            if (v.y != 0.f && j0 + 1 >= rA) m |= 2u;
            if (v.z != 0.f && j0 + 2 >= rA) m |= 4u;
            if (v.w != 0.f && j0 + 3 >= rA) m |= 8u;
            umA |= m << (4 * k);
        }
        int ib = t0B + tid + (k << 8);
        if (ib < NV / 4) {
            float4 v = __ldcs(&rpB[ib]);
            int j0 = ib << 2;
            unsigned m = 0;
            if (v.x != 0.f && j0 + 0 >= rB) m |= 1u;
            if (v.y != 0.f && j0 + 1 >= rB) m |= 2u;
            if (v.z != 0.f && j0 + 2 >= rB) m |= 4u;
            if (v.w != 0.f && j0 + 3 >= rB) m |= 8u;
            umB |= m << (4 * k);
        }
    }
    int cA = __popc(umA), cB = __popc(umB);
    int cnt = cA + cB;
    int lane = tid & 31, wid = tid >> 5;

    int dA = cA, dB = cB;
#pragma unroll
    for (int o = 16; o; o >>= 1) {
        dA += __shfl_down_sync(0xffffffffu, dA, o);
        dB += __shfl_down_sync(0xffffffffu, dB, o);
    }
    if (lane == 0) {
        if (dA) atomicAdd(&g_deg[rA], dA);
        if (dB) atomicAdd(&g_deg[rB], dB);
    }

    int inc = cnt;
#pragma unroll
    for (int o = 1; o < 32; o <<= 1) {
        int nn = __shfl_up_sync(0xffffffffu, inc, o);
        if (lane >= o) inc += nn;
    }
    __shared__ int wsum[8], wbase[8], sbase;
    if (lane == 31) wsum[wid] = inc;
    __syncthreads();
    if (tid == 0) {
        int run = 0;
        for (int w = 0; w < 8; w++) { wbase[w] = run; run += wsum[w]; }
        sbase = run ? atomicAdd(&g_ecount, run) : 0;
    }
    __syncthreads();

    int off = sbase + wbase[wid] + inc - cnt;
    unsigned m2 = umA;
    while (m2) {
        int b = __ffs(m2) - 1; m2 &= m2 - 1;
        int j = ((t0A + tid + ((b >> 2) << 8)) << 2) + (b & 3);
        if (off < ECAP) g_edges[off] = ((unsigned)rA << 13) | (unsigned)j;
        if (j > rA) atomicAdd(&g_deg[j], 1);
        off++;
    }
    m2 = umB;
    while (m2) {
        int b = __ffs(m2) - 1; m2 &= m2 - 1;
        int j = ((t0B + tid + ((b >> 2) << 8)) << 2) + (b & 3);
        if (off < ECAP) g_edges[off] = ((unsigned)rB << 13) | (unsigned)j;
        if (j > rB) atomicAdd(&g_deg[j], 1);
        off++;
    }
}

// ---------------- K2: base + edges + finalize + reset ----------------------
__global__ void __launch_bounds__(TPB) k_baseedge(float* __restrict__ out) {
    __shared__ double red[8];
    __shared__ int sdone;
    const int tid = threadIdx.x;
    const int lane = tid & 31, wid = tid >> 5;
    double acc = 0.0;

    if (blockIdx.x < NPART) {
        __shared__ int H[SPAN];
        __shared__ int sbin[PSIZE];
        int p = blockIdx.x;
        if (tid < SPAN) H[tid] = 0;
        __syncthreads();
        for (int i = tid; i < p * PSIZE; i += TPB)
            atomicAdd(&H[min(g_deg[i], SPAN - 1)], 1);
        if (tid < PSIZE) sbin[tid] = min(g_deg[p * PSIZE + tid], SPAN - 1);
        __syncthreads();

        // cross term: 32 x 256 flat loop
        for (int idx = tid; idx < (PSIZE << SH); idx += TPB) {
            int jj = idx >> SH;
            int b  = idx & (SPAN - 1);
            acc += (double)((float)H[b] * g_Tbase[(sbin[jj] << SH) + b]);
        }
        // intra-partition triangle (ii <= jj)
        for (int idx = tid; idx < NTRI; idx += TPB) {
            int jj = (int)((sqrtf(8.f * (float)idx + 1.f) - 1.f) * 0.5f);
            while ((jj + 1) * (jj + 2) / 2 <= idx) jj++;
            while (jj * (jj + 1) / 2 > idx) jj--;
            int ii = idx - jj * (jj + 1) / 2;
            acc += (double)g_Tbase[(sbin[jj] << SH) + sbin[ii]];
        }
    } else {
        int ec = min(g_ecount, ECAP);
        for (int e = (blockIdx.x - NPART) * TPB + tid; e < ec;
             e += EBLK * TPB) {
            unsigned pk = g_edges[e];
            int bi = min(g_deg[pk >> 13], SPAN - 1);
            int bj = min(g_deg[pk & 8191u], SPAN - 1);
            acc += (double)g_Tdiff[(bj << SH) + bi];
        }
    }

#pragma unroll
    for (int o = 16; o; o >>= 1) acc += __shfl_down_sync(0xffffffffu, acc, o);
    if (lane == 0) red[wid] = acc;
    __syncthreads();
    if (tid == 0) {
        double t = 0.0;
        for (int w = 0; w < 8; w++) t += red[w];
        if (t != 0.0) atomicAdd(&g_sum, t);
        __threadfence();
        sdone = atomicAdd(&g_done, 1);
    }
    __syncthreads();

    // last-finishing block: emit result and reset all scratch for next replay
    if (sdone == GRID_BE - 1) {
        for (int i = tid; i < NV; i += TPB) g_deg[i] = 0;
        if (tid == 0) {
            out[0] = -(float)g_sum;
            g_sum = 0.0;
            g_ecount = 0;
            g_done = 0;
        }
    }
}

// ---------------- launch: TWO kernel nodes ----------------
extern "C" void kernel_launch(void* const* d_in, const int* in_sizes, int n_in,
                              void* d_out, int out_size) {
    const float* params = (const float*)d_in[0];  // [3]
    const float* graph  = (const float*)d_in[1];  // [8192*8192]
    k_main<<<NPAIRS + TFILL, TPB>>>(graph, params);
    k_baseedge<<<GRID_BE, TPB>>>((float*)d_out);
}

// round 10
// speedup vs baseline: 1.4448x; 1.0093x over previous
#include <cuda_runtime.h>
#include <cuda_bf16.h>

#define NV 8192
#define EPSV 1e-5f
#define SPAN 256            /* fixed bin range: deg in [0,255], no minmax pass */
#define SH 8                /* table row stride = 256, compile-time */
#define ECAP (1 << 22)
#define TPB 256
#define NPAIRS (NV / 2)     /* 4096 streaming blocks */
#define TFILL 64            /* table-fill blocks appended to k_main */
#define NPART 256           /* base-term partition blocks */
#define PSIZE 32            /* NV / NPART */
#define NTRI (PSIZE * (PSIZE + 1) / 2)
#define EBLK 448
#define GRID_BE (NPART + EBLK)

// ---------- device state (static zero-init; reset by k_baseedge finalizer) --
__device__ int      g_deg[NV];
__device__ unsigned g_edges[ECAP];
__device__ int      g_ecount;
__device__ int      g_done;
__device__ double   g_sum;
__device__ float    g_Tbase[SPAN * SPAN];   // log(1-p+eps),   [bj<<8 | bi]
__device__ float    g_Tdiff[SPAN * SPAN];   // log(p+eps)-log(1-p+eps)

// ---------------- K1: table fill (blocks 0..63) + paired-row stream --------
__global__ void __launch_bounds__(TPB) k_main(const float* __restrict__ g,
                                              const float* __restrict__ params) {
    const int tid = threadIdx.x;

    if (blockIdx.x < TFILL) {               // ---- table fill: 4 entries/thread
        float alpha = params[0], beta = params[1], sigma = params[2];
        for (int idx = blockIdx.x * TPB + tid; idx < SPAN * SPAN;
             idx += TFILL * TPB) {
            int b = idx >> SH;              // j-side bin (beta)
            int a = idx & (SPAN - 1);       // i-side bin (alpha)
            float s = alpha * (float)a + beta * (float)b + sigma;
            float p = 1.f / (1.f + expf(s));
            float l0 = logf(1.f - p + EPSV);
            g_Tbase[idx] = l0;
            g_Tdiff[idx] = logf(p + EPSV) - l0;
        }
        return;
    }

    // ---- paired-row upper-triangle stream (validated R4/R5/R9 body) -------
    int pair = blockIdx.x - TFILL;
    int rA = pair, rB = NV - 1 - pair;
    const float4* rpA = (const float4*)(g + (size_t)rA * NV);
    const float4* rpB = (const float4*)(g + (size_t)rB * NV);
    int t0A = rA >> 2, t0B = rB >> 2;
    unsigned umA = 0, umB = 0;
#pragma unroll
    for (int k = 0; k < 8; k++) {
        int ia = t0A + tid + (k << 8);
        if (ia < NV / 4) {
            float4 v = __ldcs(&rpA[ia]);
            int j0 = ia << 2;
            unsigned m = 0;
            if (v.x != 0.f && j0 + 0 >= rA) m |= 1u;
            if (v.y != 0.f && j0 + 1 >= rA) m |= 2u;
            if (v.z != 0.f && j0 + 2 >= rA) m |= 4u;
            if (v.w != 0.f && j0 + 3 >= rA) m |= 8u;
            umA |= m << (4 * k);
        }
        int ib = t0B + tid + (k << 8);
        if (ib < NV / 4) {
            float4 v = __ldcs(&rpB[ib]);
            int j0 = ib << 2;
            unsigned m = 0;
            if (v.x != 0.f && j0 + 0 >= rB) m |= 1u;
            if (v.y != 0.f && j0 + 1 >= rB) m |= 2u;
            if (v.z != 0.f && j0 + 2 >= rB) m |= 4u;
            if (v.w != 0.f && j0 + 3 >= rB) m |= 8u;
            umB |= m << (4 * k);
        }
    }
    int cA = __popc(umA), cB = __popc(umB);
    int cnt = cA + cB;
    int lane = tid & 31, wid = tid >> 5;

    int dA = cA, dB = cB;
#pragma unroll
    for (int o = 16; o; o >>= 1) {
        dA += __shfl_down_sync(0xffffffffu, dA, o);
        dB += __shfl_down_sync(0xffffffffu, dB, o);
    }
    if (lane == 0) {
        if (dA) atomicAdd(&g_deg[rA], dA);
        if (dB) atomicAdd(&g_deg[rB], dB);
    }

    int inc = cnt;
#pragma unroll
    for (int o = 1; o < 32; o <<= 1) {
        int nn = __shfl_up_sync(0xffffffffu, inc, o);
        if (lane >= o) inc += nn;
    }
    __shared__ int wsum[8], wbase[8], sbase;
    if (lane == 31) wsum[wid] = inc;
    __syncthreads();
    if (tid == 0) {
        int run = 0;
        for (int w = 0; w < 8; w++) { wbase[w] = run; run += wsum[w]; }
        sbase = run ? atomicAdd(&g_ecount, run) : 0;
    }
    __syncthreads();

    int off = sbase + wbase[wid] + inc - cnt;
    unsigned m2 = umA;
    while (m2) {
        int b = __ffs(m2) - 1; m2 &= m2 - 1;
        int j = ((t0A + tid + ((b >> 2) << 8)) << 2) + (b & 3);
        if (off < ECAP) g_edges[off] = ((unsigned)rA << 13) | (unsigned)j;
        if (j > rA) atomicAdd(&g_deg[j], 1);
        off++;
    }
    m2 = umB;
    while (m2) {
        int b = __ffs(m2) - 1; m2 &= m2 - 1;
        int j = ((t0B + tid + ((b >> 2) << 8)) << 2) + (b & 3);
        if (off < ECAP) g_edges[off] = ((unsigned)rB << 13) | (unsigned)j;
        if (j > rB) atomicAdd(&g_deg[j], 1);
        off++;
    }
}

// ---------------- K2: base + edges + finalize + reset ----------------------
// FP32 partial accumulation (same-sign terms, short chains); double only at
// the block reduction. Cross term exploits layout: thread tid owns table
// column b = tid across all PSIZE j's, so H[tid] is loaded once.
__global__ void __launch_bounds__(TPB) k_baseedge(float* __restrict__ out) {
    __shared__ double red[8];
    __shared__ int sdone;
    const int tid = threadIdx.x;
    const int lane = tid & 31, wid = tid >> 5;
    double acc = 0.0;

    if (blockIdx.x < NPART) {
        __shared__ int H[SPAN];
        __shared__ int sbin[PSIZE];
        int p = blockIdx.x;
        if (tid < SPAN) H[tid] = 0;
        __syncthreads();
        for (int i = tid; i < p * PSIZE; i += TPB)
            atomicAdd(&H[min(g_deg[i], SPAN - 1)], 1);
        if (tid < PSIZE) sbin[tid] = min(g_deg[p * PSIZE + tid], SPAN - 1);
        __syncthreads();

        // cross term: thread tid owns column b = tid; H load hoisted,
        // two independent float accumulator chains over the 32 rows.
        float hb = (float)H[tid];
        float s0 = 0.f, s1 = 0.f;
#pragma unroll
        for (int jj = 0; jj < PSIZE; jj += 2) {
            s0 += g_Tbase[(sbin[jj]     << SH) + tid];
            s1 += g_Tbase[(sbin[jj + 1] << SH) + tid];
        }
        float fa = hb * (s0 + s1);

        // intra-partition triangle (ii <= jj), ~2 iterations/thread
        for (int idx = tid; idx < NTRI; idx += TPB) {
            int jj = (int)((sqrtf(8.f * (float)idx + 1.f) - 1.f) * 0.5f);
            while ((jj + 1) * (jj + 2) / 2 <= idx) jj++;
            while (jj * (jj + 1) / 2 > idx) jj--;
            int ii = idx - jj * (jj + 1) / 2;
            fa += g_Tbase[(sbin[jj] << SH) + sbin[ii]];
        }
        acc = (double)fa;
    } else {
        int ec = min(g_ecount, ECAP);
        float fa = 0.f;
        for (int e = (blockIdx.x - NPART) * TPB + tid; e < ec;
             e += EBLK * TPB) {
            unsigned pk = g_edges[e];
            int bi = min(g_deg[pk >> 13], SPAN - 1);
            int bj = min(g_deg[pk & 8191u], SPAN - 1);
            fa += g_Tdiff[(bj << SH) + bi];
        }
        acc = (double)fa;
    }

#pragma unroll
    for (int o = 16; o; o >>= 1) acc += __shfl_down_sync(0xffffffffu, acc, o);
    if (lane == 0) red[wid] = acc;
    __syncthreads();
    if (tid == 0) {
        double t = 0.0;
        for (int w = 0; w < 8; w++) t += red[w];
        if (t != 0.0) atomicAdd(&g_sum, t);
        __threadfence();
        sdone = atomicAdd(&g_done, 1);
    }
    __syncthreads();

    // last-finishing block: emit result and reset all scratch for next replay
    if (sdone == GRID_BE - 1) {
        for (int i = tid; i < NV; i += TPB) g_deg[i] = 0;
        if (tid == 0) {
            out[0] = -(float)g_sum;
            g_sum = 0.0;
            g_ecount = 0;
            g_done = 0;
        }
    }
}

// ---------------- launch: TWO kernel nodes ----------------
extern "C" void kernel_launch(void* const* d_in, const int* in_sizes, int n_in,
                              void* d_out, int out_size) {
    const float* params = (const float*)d_in[0];  // [3]
    const float* graph  = (const float*)d_in[1];  // [8192*8192]
    k_main<<<NPAIRS + TFILL, TPB>>>(graph, params);
    k_baseedge<<<GRID_BE, TPB>>>((float*)d_out);
}

// round 11
// speedup vs baseline: 1.4504x; 1.0039x over previous
#include <cuda_runtime.h>
#include <cuda_bf16.h>

#define NV 8192
#define EPSV 1e-5f
#define SPAN 256            /* fixed bin range: deg in [0,255], no minmax pass */
#define SH 8                /* table row stride = 256, compile-time */
#define ECAP (1 << 22)
#define TPB 256
#define NPAIRS (NV / 2)     /* 4096 streaming blocks */
#define TFILL 64            /* table-fill blocks appended to k_main */
#define NPART 256           /* base-term partition blocks */
#define PSIZE 32            /* NV / NPART */
#define NTRI (PSIZE * (PSIZE + 1) / 2)
#define EBLK 448
#define GRID_BE (NPART + EBLK)

// ---------- device state (static zero-init; reset by k_baseedge finalizer) --
__device__ int      g_deg[NV];
__device__ unsigned g_edges[ECAP];
__device__ int      g_ecount;
__device__ int      g_done;
__device__ double   g_part[GRID_BE];        // per-block partials: NO fp64 atomics
__device__ float    g_Tbase[SPAN * SPAN];   // log(1-p+eps),   [bj<<8 | bi]
__device__ float    g_Tdiff[SPAN * SPAN];   // log(p+eps)-log(1-p+eps)

// ---------------- K1: table fill (blocks 0..63) + paired-row stream --------
__global__ void __launch_bounds__(TPB) k_main(const float* __restrict__ g,
                                              const float* __restrict__ params) {
    const int tid = threadIdx.x;

    if (blockIdx.x < TFILL) {               // ---- table fill: 4 entries/thread
        float alpha = params[0], beta = params[1], sigma = params[2];
        for (int idx = blockIdx.x * TPB + tid; idx < SPAN * SPAN;
             idx += TFILL * TPB) {
            int b = idx >> SH;              // j-side bin (beta)
            int a = idx & (SPAN - 1);       // i-side bin (alpha)
            float s = alpha * (float)a + beta * (float)b + sigma;
            float p = 1.f / (1.f + expf(s));
            float l0 = logf(1.f - p + EPSV);
            g_Tbase[idx] = l0;
            g_Tdiff[idx] = logf(p + EPSV) - l0;
        }
        return;
    }

    // ---- paired-row upper-triangle stream (validated R4-R10 body) ---------
    int pair = blockIdx.x - TFILL;
    int rA = pair, rB = NV - 1 - pair;
    const float4* rpA = (const float4*)(g + (size_t)rA * NV);
    const float4* rpB = (const float4*)(g + (size_t)rB * NV);
    int t0A = rA >> 2, t0B = rB >> 2;
    unsigned umA = 0, umB = 0;
#pragma unroll
    for (int k = 0; k < 8; k++) {
        int ia = t0A + tid + (k << 8);
        if (ia < NV / 4) {
            float4 v = __ldcs(&rpA[ia]);
            int j0 = ia << 2;
            unsigned m = 0;
            if (v.x != 0.f && j0 + 0 >= rA) m |= 1u;
            if (v.y != 0.f && j0 + 1 >= rA) m |= 2u;
            if (v.z != 0.f && j0 + 2 >= rA) m |= 4u;
            if (v.w != 0.f && j0 + 3 >= rA) m |= 8u;
            umA |= m << (4 * k);
        }
        int ib = t0B + tid + (k << 8);
        if (ib < NV / 4) {
            float4 v = __ldcs(&rpB[ib]);
            int j0 = ib << 2;
            unsigned m = 0;
            if (v.x != 0.f && j0 + 0 >= rB) m |= 1u;
            if (v.y != 0.f && j0 + 1 >= rB) m |= 2u;
            if (v.z != 0.f && j0 + 2 >= rB) m |= 4u;
            if (v.w != 0.f && j0 + 3 >= rB) m |= 8u;
            umB |= m << (4 * k);
        }
    }
    int cA = __popc(umA), cB = __popc(umB);
    int cnt = cA + cB;
    int lane = tid & 31, wid = tid >> 5;

    int dA = cA, dB = cB;
#pragma unroll
    for (int o = 16; o; o >>= 1) {
        dA += __shfl_down_sync(0xffffffffu, dA, o);
        dB += __shfl_down_sync(0xffffffffu, dB, o);
    }
    if (lane == 0) {
        if (dA) atomicAdd(&g_deg[rA], dA);
        if (dB) atomicAdd(&g_deg[rB], dB);
    }

    int inc = cnt;
#pragma unroll
    for (int o = 1; o < 32; o <<= 1) {
        int nn = __shfl_up_sync(0xffffffffu, inc, o);
        if (lane >= o) inc += nn;
    }
    __shared__ int wsum[8], wbase[8], sbase;
    if (lane == 31) wsum[wid] = inc;
    __syncthreads();
    if (tid == 0) {
        int run = 0;
        for (int w = 0; w < 8; w++) { wbase[w] = run; run += wsum[w]; }
        sbase = run ? atomicAdd(&g_ecount, run) : 0;
    }
    __syncthreads();

    int off = sbase + wbase[wid] + inc - cnt;
    unsigned m2 = umA;
    while (m2) {
        int b = __ffs(m2) - 1; m2 &= m2 - 1;
        int j = ((t0A + tid + ((b >> 2) << 8)) << 2) + (b & 3);
        if (off < ECAP) g_edges[off] = ((unsigned)rA << 13) | (unsigned)j;
        if (j > rA) atomicAdd(&g_deg[j], 1);
        off++;
    }
    m2 = umB;
    while (m2) {
        int b = __ffs(m2) - 1; m2 &= m2 - 1;
        int j = ((t0B + tid + ((b >> 2) << 8)) << 2) + (b & 3);
        if (off < ECAP) g_edges[off] = ((unsigned)rB << 13) | (unsigned)j;
        if (j > rB) atomicAdd(&g_deg[j], 1);
        off++;
    }
}

// ---------------- K2: base + edges; per-block STG partials, no fp64 atomics -
__global__ void __launch_bounds__(TPB) k_baseedge(float* __restrict__ out) {
    __shared__ double red[8];
    __shared__ int sdone;
    const int tid = threadIdx.x;
    const int lane = tid & 31, wid = tid >> 5;
    double acc = 0.0;

    if (blockIdx.x < NPART) {
        __shared__ int H[SPAN];
        __shared__ int sbin[PSIZE];
        int p = blockIdx.x;
        if (tid < SPAN) H[tid] = 0;
        __syncthreads();
        for (int i = tid; i < p * PSIZE; i += TPB)
            atomicAdd(&H[min(g_deg[i], SPAN - 1)], 1);
        if (tid < PSIZE) sbin[tid] = min(g_deg[p * PSIZE + tid], SPAN - 1);
        __syncthreads();

        // cross term: thread tid owns column b = tid; H load hoisted
        float hb = (float)H[tid];
        float s0 = 0.f, s1 = 0.f;
#pragma unroll
        for (int jj = 0; jj < PSIZE; jj += 2) {
            s0 += g_Tbase[(sbin[jj]     << SH) + tid];
            s1 += g_Tbase[(sbin[jj + 1] << SH) + tid];
        }
        float fa = hb * (s0 + s1);

        // intra-partition triangle (ii <= jj)
        for (int idx = tid; idx < NTRI; idx += TPB) {
            int jj = (int)((sqrtf(8.f * (float)idx + 1.f) - 1.f) * 0.5f);
            while ((jj + 1) * (jj + 2) / 2 <= idx) jj++;
            while (jj * (jj + 1) / 2 > idx) jj--;
            int ii = idx - jj * (jj + 1) / 2;
            fa += g_Tbase[(sbin[jj] << SH) + sbin[ii]];
        }
        acc = (double)fa;
    } else {
        int ec = min(g_ecount, ECAP);
        float fa = 0.f;
        for (int e = (blockIdx.x - NPART) * TPB + tid; e < ec;
             e += EBLK * TPB) {
            unsigned pk = g_edges[e];
            int bi = min(g_deg[pk >> 13], SPAN - 1);
            int bj = min(g_deg[pk & 8191u], SPAN - 1);
            fa += g_Tdiff[(bj << SH) + bi];
        }
        acc = (double)fa;
    }

#pragma unroll
    for (int o = 16; o; o >>= 1) acc += __shfl_down_sync(0xffffffffu, acc, o);
    if (lane == 0) red[wid] = acc;
    __syncthreads();
    if (tid == 0) {
        double t = 0.0;
        for (int w = 0; w < 8; w++) t += red[w];
        g_part[blockIdx.x] = t;            // plain STG — no cross-block RMW
        __threadfence();
        sdone = atomicAdd(&g_done, 1);     // cheap int counter, ~1 cyc/op
    }
    __syncthreads();

    // last-arriving block: reduce partials, emit, reset scratch for replay
    if (sdone == GRID_BE - 1) {
        double t = 0.0;
        for (int i = tid; i < GRID_BE; i += TPB) t += g_part[i];
#pragma unroll
        for (int o = 16; o; o >>= 1) t += __shfl_down_sync(0xffffffffu, t, o);
        if (lane == 0) red[wid] = t;
        for (int i = tid; i < NV; i += TPB) g_deg[i] = 0;
        __syncthreads();
        if (tid == 0) {
            double s = 0.0;
            for (int w = 0; w < 8; w++) s += red[w];
            out[0] = -(float)s;
            g_ecount = 0;
            g_done = 0;
        }
    }
}

// ---------------- launch: TWO kernel nodes ----------------
extern "C" void kernel_launch(void* const* d_in, const int* in_sizes, int n_in,
                              void* d_out, int out_size) {
    const float* params = (const float*)d_in[0];  // [3]
    const float* graph  = (const float*)d_in[1];  // [8192*8192]
    k_main<<<NPAIRS + TFILL, TPB>>>(graph, params);
    k_baseedge<<<GRID_BE, TPB>>>((float*)d_out);
}